// round 7
// baseline (speedup 1.0000x reference)
#include <cuda_runtime.h>
#include <cuda_bf16.h>
#include <math.h>

// ---------------- problem constants ----------------
#define KBINS 125
#define HROW (KBINS * 32)            // 4000 floats per node H row
#define N0 131072
#define N1 65536
#define N2 32768
#define N3 16384
#define B8 16384
#define E1 1703936
#define E2 851968
#define E3 425984
#define NBATCH 2048
#define CHUNK 4096                   // nodes per L2-resident H chunk (64 MB)

// ---------------- static scratch ----------------
__device__ float g_p0[N1];
__device__ float g_h1[N1 * 32];
__device__ float g_p1[N2 * 32];
__device__ float g_h2[N2 * 32];
__device__ float g_p2[N3 * 32];
__device__ float g_h3[N3 * 32];
__device__ float g_p3[B8 * 32];

__device__ float g_H1[(size_t)N1 * KBINS];         // 32 MB (conv1, cin=1)
__device__ float g_Hb[(size_t)CHUNK * HROW];       // 64 MB shared chunk buffer conv2/3

__device__ int    g_cnt1[N1]; __device__ int g_off1[N1 + 1]; __device__ int g_cur1[N1];
__device__ int    g_cnt2[N2]; __device__ int g_off2[N2 + 1]; __device__ int g_cur2[N2];
__device__ int    g_cnt3[N3]; __device__ int g_off3[N3 + 1]; __device__ int g_cur3[N3];
__device__ int    g_src1[E1]; __device__ float4 g_ps1[E1];
__device__ int    g_src2[E2]; __device__ float4 g_ps2[E2];
__device__ int    g_src3[E3]; __device__ float4 g_ps3[E3];

// ---------------- layer traits (global addressing stays device-side) ----------------
template <int L> struct BT;
template <> struct BT<1> {
    static const int N = N1, E = E1;
    static __device__ __forceinline__ int*    cnt()  { return g_cnt1; }
    static __device__ __forceinline__ int*    off()  { return g_off1; }
    static __device__ __forceinline__ int*    cur()  { return g_cur1; }
    static __device__ __forceinline__ int*    srcS() { return g_src1; }
    static __device__ __forceinline__ float4* psS()  { return g_ps1; }
    static __device__ __forceinline__ float*  hin()  { return g_p0; }
    static __device__ __forceinline__ float*  hout() { return g_h1; }
};
template <> struct BT<2> {
    static const int N = N2, E = E2;
    static __device__ __forceinline__ int*    cnt()  { return g_cnt2; }
    static __device__ __forceinline__ int*    off()  { return g_off2; }
    static __device__ __forceinline__ int*    cur()  { return g_cur2; }
    static __device__ __forceinline__ int*    srcS() { return g_src2; }
    static __device__ __forceinline__ float4* psS()  { return g_ps2; }
    static __device__ __forceinline__ float*  hin()  { return g_p1; }
    static __device__ __forceinline__ float*  hout() { return g_h2; }
};
template <> struct BT<3> {
    static const int N = N3, E = E3;
    static __device__ __forceinline__ int*    cnt()  { return g_cnt3; }
    static __device__ __forceinline__ int*    off()  { return g_off3; }
    static __device__ __forceinline__ int*    cur()  { return g_cur3; }
    static __device__ __forceinline__ int*    srcS() { return g_src3; }
    static __device__ __forceinline__ float4* psS()  { return g_ps3; }
    static __device__ __forceinline__ float*  hin()  { return g_p2; }
    static __device__ __forceinline__ float*  hout() { return g_h3; }
};

// pool selectors
template <int L> __device__ __forceinline__ float* pool_in();
template <> __device__ __forceinline__ float* pool_in<1>() { return g_h1; }
template <> __device__ __forceinline__ float* pool_in<2>() { return g_h2; }
template <> __device__ __forceinline__ float* pool_in<3>() { return g_h3; }
template <int L> __device__ __forceinline__ float* pool_out();
template <> __device__ __forceinline__ float* pool_out<1>() { return g_p1; }
template <> __device__ __forceinline__ float* pool_out<2>() { return g_p2; }
template <> __device__ __forceinline__ float* pool_out<3>() { return g_p3; }

// ---------------- helpers ----------------
__device__ __forceinline__ void atomicMaxF(float* addr, float v) {
    if (__float_as_int(v) >= 0) atomicMax((int*)addr, __float_as_int(v));
    else                        atomicMin((unsigned int*)addr, __float_as_uint(v));
}

__device__ __forceinline__ void basis8(float px, float py, float pz, float* wc, int* flat) {
    float v0 = px * 4.0f, v1 = py * 4.0f, v2 = pz * 4.0f;
    float k0 = fminf(fmaxf(floorf(v0), 0.0f), 3.0f);
    float k1 = fminf(fmaxf(floorf(v1), 0.0f), 3.0f);
    float k2 = fminf(fmaxf(floorf(v2), 0.0f), 3.0f);
    float f0 = v0 - k0, f1 = v1 - k1, f2 = v2 - k2;
    int i0 = (int)k0, i1 = (int)k1, i2 = (int)k2;
#pragma unroll
    for (int c = 0; c < 8; c++) {
        int o0 = c & 1, o1 = (c >> 1) & 1, o2 = (c >> 2) & 1;
        wc[c] = (o0 ? f0 : 1.0f - f0) * (o1 ? f1 : 1.0f - f1) * (o2 ? f2 : 1.0f - f2);
        flat[c] = ((i0 + o0) * 5 + (i1 + o1)) * 5 + (i2 + o2);
    }
}

// ---------------- init ----------------
__global__ void k_init_all() {
    int i = blockIdx.x * blockDim.x + threadIdx.x;
    int stride = gridDim.x * blockDim.x;
    const float NEGINF = -INFINITY;
    for (int j = i; j < N1; j += stride)      { g_p0[j] = NEGINF; g_cnt1[j] = 0; }
    for (int j = i; j < N2 * 32; j += stride) g_p1[j] = NEGINF;
    for (int j = i; j < N2; j += stride)      g_cnt2[j] = 0;
    for (int j = i; j < N3 * 32; j += stride) g_p2[j] = NEGINF;
    for (int j = i; j < N3; j += stride)      g_cnt3[j] = 0;
    for (int j = i; j < B8 * 32; j += stride) g_p3[j] = NEGINF;
}

// ---------------- pools ----------------
__global__ void k_pool0(const float* __restrict__ x, const int* __restrict__ cluster) {
    int i = blockIdx.x * blockDim.x + threadIdx.x;
    if (i >= N0) return;
    atomicMaxF(&g_p0[__ldg(&cluster[i])], __ldg(&x[i]));
}
__global__ void k_fix0() {
    int i = blockIdx.x * blockDim.x + threadIdx.x;
    if (i < N1 && !isfinite(g_p0[i])) g_p0[i] = 0.0f;
}
template <int L>
__global__ void k_pool32(const int* __restrict__ cluster, int n_in) {
    int i = blockIdx.x * blockDim.x + threadIdx.x;
    if (i >= n_in * 32) return;
    int node = i >> 5, ch = i & 31;
    atomicMaxF(&pool_out<L>()[(size_t)__ldg(&cluster[node]) * 32 + ch], pool_in<L>()[i]);
}
template <int L>
__global__ void k_fix32(int n) {
    int i = blockIdx.x * blockDim.x + threadIdx.x;
    if (i < n) {
        float v = pool_out<L>()[i];
        if (!isfinite(v)) pool_out<L>()[i] = 0.0f;
    }
}

// ---------------- CSR build ----------------
template <int L>
__global__ void k_hist(const int* __restrict__ ei) {
    const int E = BT<L>::E;
    int i = blockIdx.x * blockDim.x + threadIdx.x;
    if (i >= E) return;
    atomicAdd(&BT<L>::cnt()[__ldg(&ei[E + i])], 1);
}

template <int L>
__global__ void k_scan() {
    const int N = BT<L>::N;
    const int CH = N / 1024;
    __shared__ int sums[1024];
    int t = threadIdx.x;
    int base = t * CH;
    int s = 0;
    for (int j = 0; j < CH; j++) s += BT<L>::cnt()[base + j];
    sums[t] = s;
    __syncthreads();
    for (int d = 1; d < 1024; d <<= 1) {
        int v = (t >= d) ? sums[t - d] : 0;
        __syncthreads();
        sums[t] += v;
        __syncthreads();
    }
    int run = sums[t] - s;   // exclusive prefix
    for (int j = 0; j < CH; j++) {
        BT<L>::off()[base + j] = run;
        BT<L>::cur()[base + j] = run;
        run += BT<L>::cnt()[base + j];
    }
    if (t == 1023) BT<L>::off()[N] = run;
}

template <int L>
__global__ void k_permscat(const int* __restrict__ ei, const float* __restrict__ pseudo) {
    const int E = BT<L>::E;
    int i = blockIdx.x * blockDim.x + threadIdx.x;
    if (i >= E) return;
    int dst = __ldg(&ei[E + i]);
    int pos = atomicAdd(&BT<L>::cur()[dst], 1);
    BT<L>::srcS()[pos] = __ldg(&ei[i]);
    BT<L>::psS()[pos] = make_float4(__ldg(&pseudo[3 * i]), __ldg(&pseudo[3 * i + 1]),
                                    __ldg(&pseudo[3 * i + 2]), 0.0f);
}

// ---------------- conv1 (cin=1): scatter + contraction ----------------
__global__ void k_scatter1() {
    __shared__ float Hs[8][KBINS];
    int w = threadIdx.x >> 5, lane = threadIdx.x & 31;
    int node = blockIdx.x * 8 + w;
    for (int j = lane; j < KBINS; j += 32) Hs[w][j] = 0.0f;
    __syncwarp();
    int beg = g_off1[node], end = g_off1[node + 1];
    for (int e0 = beg; e0 < end; e0 += 32) {
        int e = e0 + lane;
        if (e < end) {
            int src = g_src1[e];
            float4 ps = g_ps1[e];
            float xj = g_p0[src];
            float wc[8]; int flat[8];
            basis8(ps.x, ps.y, ps.z, wc, flat);
#pragma unroll
            for (int c = 0; c < 8; c++) atomicAdd(&Hs[w][flat[c]], wc[c] * xj);
        }
    }
    __syncwarp();
    for (int j = lane; j < KBINS; j += 32) g_H1[(size_t)node * KBINS + j] = Hs[w][j];
}

__global__ void k_gemm1(const float* __restrict__ W1, const float* __restrict__ root1,
                        const float* __restrict__ b1) {
    __shared__ float W1s[KBINS * 32];
    int tid = threadIdx.x;
    for (int idx = tid; idx < KBINS * 32; idx += 256) W1s[idx] = __ldg(&W1[idx]);
    __syncthreads();
    int w = tid >> 5, lane = tid & 31;
    int node = blockIdx.x * 8 + w;
    const float* Hrow = &g_H1[(size_t)node * KBINS];
    float acc = 0.0f;
#pragma unroll 5
    for (int k = 0; k < KBINS; k++) acc += Hrow[k] * W1s[k * 32 + lane];
    int deg = g_off1[node + 1] - g_off1[node];
    float d = (float)(deg > 0 ? deg : 1);
    float v = acc / d + g_p0[node] * __ldg(&root1[lane]) + __ldg(&b1[lane]);
    g_h1[(size_t)node * 32 + lane] = v > 0.0f ? v : expm1f(v);
}

// ---------------- conv2/3 scatter: 4 warps/block, chunked into g_Hb ----------------
template <int L>
__global__ void k_scatter32(int nodeBase) {
    __shared__ float Hs[4][HROW];
    int w = threadIdx.x >> 5, lane = threadIdx.x & 31;
    int node = nodeBase + blockIdx.x * 4 + w;
    float* hrow = Hs[w];
#pragma unroll 4
    for (int j = lane; j < HROW; j += 32) hrow[j] = 0.0f;
    __syncwarp();
    const float* hin = BT<L>::hin();
    const int* srcS = BT<L>::srcS();
    const float4* psS = BT<L>::psS();
    int beg = BT<L>::off()[node], end = BT<L>::off()[node + 1];
    if (beg < end) {
        // software-pipelined edge loop: prefetch next (ps, xv) while processing current
        float4 ps = psS[beg];
        float xv = hin[(size_t)srcS[beg] * 32 + lane];
        for (int e = beg; e < end; e++) {
            float4 ps_n = ps;
            float xv_n = 0.0f;
            if (e + 1 < end) {
                int s = srcS[e + 1];
                ps_n = psS[e + 1];
                xv_n = hin[(size_t)s * 32 + lane];
            }
            float wc[8]; int flat[8];
            basis8(ps.x, ps.y, ps.z, wc, flat);
#pragma unroll
            for (int c = 0; c < 8; c++) hrow[flat[c] * 32 + lane] += wc[c] * xv;
            ps = ps_n; xv = xv_n;
        }
    }
    __syncwarp();
    float* Hg = g_Hb + (size_t)(node - nodeBase) * HROW;
#pragma unroll 4
    for (int j = lane; j < HROW; j += 32) Hg[j] = hrow[j];
}

// ---------------- conv2/3 contraction: 32 nodes/block from L2-resident g_Hb ----------------
template <int L>
__global__ void k_gemm32(const float* __restrict__ W, const float* __restrict__ root,
                         const float* __restrict__ bias, int nodeBase) {
    __shared__ float Ws[1024];      // W[k]: [i][o]
    __shared__ float Hs[32 * 32];   // 32 node-rows of 32
    int tid = threadIdx.x;          // 256
    int w = tid >> 5, lane = tid & 31;
    int local0 = blockIdx.x * 32;   // first local node of this block within the chunk
    float acc[4];
#pragma unroll
    for (int n = 0; n < 4; n++) acc[n] = 0.0f;

    for (int k = 0; k < KBINS; k++) {
        ((float4*)Ws)[tid] = __ldg(&((const float4*)(W + (size_t)k * 1024))[tid]);
        {   // stage 32 rows x 32 ch of H for this k: 256 float4
            int nd = tid >> 3, q = tid & 7;
            ((float4*)Hs)[tid] =
                *(const float4*)&g_Hb[((size_t)(local0 + nd) * KBINS + k) * 32 + q * 4];
        }
        __syncthreads();
#pragma unroll
        for (int i4 = 0; i4 < 8; i4++) {
            float w0 = Ws[(i4 * 4 + 0) * 32 + lane];
            float w1 = Ws[(i4 * 4 + 1) * 32 + lane];
            float w2 = Ws[(i4 * 4 + 2) * 32 + lane];
            float w3 = Ws[(i4 * 4 + 3) * 32 + lane];
#pragma unroll
            for (int n = 0; n < 4; n++) {
                float4 hv = ((float4*)Hs)[(w * 4 + n) * 8 + i4];   // broadcast within warp
                acc[n] += hv.x * w0 + hv.y * w1 + hv.z * w2 + hv.w * w3;
            }
        }
        __syncthreads();
    }
    // divide by degree
#pragma unroll
    for (int n = 0; n < 4; n++) {
        int node = nodeBase + local0 + w * 4 + n;
        int deg = BT<L>::off()[node + 1] - BT<L>::off()[node];
        acc[n] /= (float)(deg > 0 ? deg : 1);
    }
    // root term
    ((float4*)Ws)[tid] = __ldg(&((const float4*)root)[tid]);
    const float* hin = BT<L>::hin();
    {
        int nd = tid >> 3, q = tid & 7;
        ((float4*)Hs)[tid] =
            *(const float4*)&hin[(size_t)(nodeBase + local0 + nd) * 32 + q * 4];
    }
    __syncthreads();
#pragma unroll
    for (int i4 = 0; i4 < 8; i4++) {
        float w0 = Ws[(i4 * 4 + 0) * 32 + lane];
        float w1 = Ws[(i4 * 4 + 1) * 32 + lane];
        float w2 = Ws[(i4 * 4 + 2) * 32 + lane];
        float w3 = Ws[(i4 * 4 + 3) * 32 + lane];
#pragma unroll
        for (int n = 0; n < 4; n++) {
            float4 hv = ((float4*)Hs)[(w * 4 + n) * 8 + i4];
            acc[n] += hv.x * w0 + hv.y * w1 + hv.z * w2 + hv.w * w3;
        }
    }
    float bv = __ldg(&bias[lane]);
    float* hout = BT<L>::hout();
#pragma unroll
    for (int n = 0; n < 4; n++) {
        float v = acc[n] + bv;
        hout[(size_t)(nodeBase + local0 + w * 4 + n) * 32 + lane] = v > 0.0f ? v : expm1f(v);
    }
}

// ---------------- FC head + log_softmax ----------------
__global__ void k_fc_head(const float* __restrict__ fcw, const float* __restrict__ fcb,
                          float* __restrict__ out) {
    __shared__ float hs[256];
    __shared__ float lg[10];
    __shared__ float lse;
    int b = blockIdx.x;
    int t = threadIdx.x;
    hs[t] = g_p3[(size_t)b * 256 + t];
    __syncthreads();
    if (t < 10) {
        float s = __ldg(&fcb[t]);
#pragma unroll 8
        for (int i = 0; i < 256; i++) s += hs[i] * __ldg(&fcw[i * 10 + t]);
        lg[t] = s;
    }
    __syncthreads();
    if (t == 0) {
        float m = lg[0];
        for (int j = 1; j < 10; j++) m = fmaxf(m, lg[j]);
        float se = 0.0f;
        for (int j = 0; j < 10; j++) se += expf(lg[j] - m);
        lse = m + logf(se);
    }
    __syncthreads();
    if (t < 10) out[b * 10 + t] = lg[t] - lse;
}

// ---------------- launcher ----------------
static inline int cdiv(long long a, int b) { return (int)((a + b - 1) / b); }

extern "C" void kernel_launch(void* const* d_in, const int* in_sizes, int n_in,
                              void* d_out, int out_size) {
    const float* x        = (const float*)d_in[0];
    const int*   cluster0 = (const int*)d_in[1];
    const int*   ei1      = (const int*)d_in[2];
    const float* pseudo1  = (const float*)d_in[3];
    const int*   cluster1 = (const int*)d_in[4];
    const int*   ei2      = (const int*)d_in[5];
    const float* pseudo2  = (const float*)d_in[6];
    const int*   cluster2 = (const int*)d_in[7];
    const int*   ei3      = (const int*)d_in[8];
    const float* pseudo3  = (const float*)d_in[9];
    const int*   cluster3 = (const int*)d_in[10];
    const float* W1       = (const float*)d_in[11];
    const float* root1    = (const float*)d_in[12];
    const float* b1       = (const float*)d_in[13];
    const float* W2       = (const float*)d_in[14];
    const float* root2    = (const float*)d_in[15];
    const float* b2       = (const float*)d_in[16];
    const float* W3       = (const float*)d_in[17];
    const float* root3    = (const float*)d_in[18];
    const float* b3       = (const float*)d_in[19];
    const float* fcw      = (const float*)d_in[20];
    const float* fcb      = (const float*)d_in[21];
    float* out = (float*)d_out;

    const int TB = 256;

    k_init_all<<<512, TB>>>();

    // CSR builds
    k_hist<1><<<cdiv(E1, TB), TB>>>(ei1);
    k_hist<2><<<cdiv(E2, TB), TB>>>(ei2);
    k_hist<3><<<cdiv(E3, TB), TB>>>(ei3);
    k_scan<1><<<1, 1024>>>();
    k_scan<2><<<1, 1024>>>();
    k_scan<3><<<1, 1024>>>();
    k_permscat<1><<<cdiv(E1, TB), TB>>>(ei1, pseudo1);
    k_permscat<2><<<cdiv(E2, TB), TB>>>(ei2, pseudo2);
    k_permscat<3><<<cdiv(E3, TB), TB>>>(ei3, pseudo3);

    // ---- level 1 ----
    k_pool0<<<cdiv(N0, TB), TB>>>(x, cluster0);
    k_fix0<<<cdiv(N1, TB), TB>>>();
    k_scatter1<<<N1 / 8, TB>>>();
    k_gemm1<<<N1 / 8, TB>>>(W1, root1, b1);

    // ---- level 2 ----
    k_pool32<1><<<cdiv(N1 * 32, TB), TB>>>(cluster1, N1);
    k_fix32<1><<<cdiv(N2 * 32, TB), TB>>>(N2 * 32);
    for (int c = 0; c < N2 / CHUNK; c++) {
        k_scatter32<2><<<CHUNK / 4, 128>>>(c * CHUNK);
        k_gemm32<2><<<CHUNK / 32, 256>>>(W2, root2, b2, c * CHUNK);
    }

    // ---- level 3 ----
    k_pool32<2><<<cdiv(N2 * 32, TB), TB>>>(cluster2, N2);
    k_fix32<2><<<cdiv(N3 * 32, TB), TB>>>(N3 * 32);
    for (int c = 0; c < N3 / CHUNK; c++) {
        k_scatter32<3><<<CHUNK / 4, 128>>>(c * CHUNK);
        k_gemm32<3><<<CHUNK / 32, 256>>>(W3, root3, b3, c * CHUNK);
    }

    // ---- final pool + FC ----
    k_pool32<3><<<cdiv(N3 * 32, TB), TB>>>(cluster3, N3);
    k_fix32<3><<<cdiv(B8 * 32, TB), TB>>>(B8 * 32);
    k_fc_head<<<NBATCH, 256>>>(fcw, fcb, out);
}

// round 8
// speedup vs baseline: 2.6068x; 2.6068x over previous
#include <cuda_runtime.h>
#include <cuda_bf16.h>
#include <math.h>

// ---------------- problem constants ----------------
#define KBINS 125
#define HROW (KBINS * 32)
#define N0 131072
#define N1 65536
#define N2 32768
#define N3 16384
#define B8 16384
#define E1 1703936
#define E2 851968
#define E3 425984
#define NBATCH 2048

// ---------------- static scratch ----------------
__device__ float g_p0[N1];
__device__ float g_h1[N1 * 32];
__device__ float g_p1[N2 * 32];
__device__ float g_h2[N2 * 32];
__device__ float g_p2[N3 * 32];
__device__ float g_h3[N3 * 32];
__device__ float g_p3[B8 * 32];

__device__ float g_H2[(size_t)N2 * HROW];       // 524 MB
__device__ float g_H3[(size_t)N3 * HROW];       // 262 MB
__device__ float2 g_Wp2[KBINS * 512];           // repacked W2: [k][i/2][o] pairs
__device__ float2 g_Wp3[KBINS * 512];

__device__ int    g_cnt1[N1]; __device__ int g_off1[N1 + 1]; __device__ int g_cur1[N1];
__device__ int    g_cnt2[N2]; __device__ int g_off2[N2 + 1]; __device__ int g_cur2[N2];
__device__ int    g_cnt3[N3]; __device__ int g_off3[N3 + 1]; __device__ int g_cur3[N3];
__device__ int    g_src1[E1]; __device__ float4 g_ps1[E1];
__device__ int    g_src2[E2]; __device__ float4 g_ps2[E2];
__device__ int    g_src3[E3]; __device__ float4 g_ps3[E3];

// ---------------- layer traits ----------------
template <int L> struct BT;
template <> struct BT<1> {
    static const int N = N1, E = E1;
    static __device__ __forceinline__ int*    cnt()  { return g_cnt1; }
    static __device__ __forceinline__ int*    off()  { return g_off1; }
    static __device__ __forceinline__ int*    cur()  { return g_cur1; }
    static __device__ __forceinline__ int*    srcS() { return g_src1; }
    static __device__ __forceinline__ float4* psS()  { return g_ps1; }
};
template <> struct BT<2> {
    static const int N = N2, E = E2;
    static __device__ __forceinline__ int*    cnt()  { return g_cnt2; }
    static __device__ __forceinline__ int*    off()  { return g_off2; }
    static __device__ __forceinline__ int*    cur()  { return g_cur2; }
    static __device__ __forceinline__ int*    srcS() { return g_src2; }
    static __device__ __forceinline__ float4* psS()  { return g_ps2; }
    static __device__ __forceinline__ float*  H()    { return g_H2; }
    static __device__ __forceinline__ float2* Wp()   { return g_Wp2; }
    static __device__ __forceinline__ float*  hin()  { return g_p1; }
    static __device__ __forceinline__ float*  hout() { return g_h2; }
};
template <> struct BT<3> {
    static const int N = N3, E = E3;
    static __device__ __forceinline__ int*    cnt()  { return g_cnt3; }
    static __device__ __forceinline__ int*    off()  { return g_off3; }
    static __device__ __forceinline__ int*    cur()  { return g_cur3; }
    static __device__ __forceinline__ int*    srcS() { return g_src3; }
    static __device__ __forceinline__ float4* psS()  { return g_ps3; }
    static __device__ __forceinline__ float*  H()    { return g_H3; }
    static __device__ __forceinline__ float2* Wp()   { return g_Wp3; }
    static __device__ __forceinline__ float*  hin()  { return g_p2; }
    static __device__ __forceinline__ float*  hout() { return g_h3; }
};

// pool selectors
template <int L> __device__ __forceinline__ float* pool_in();
template <> __device__ __forceinline__ float* pool_in<1>() { return g_h1; }
template <> __device__ __forceinline__ float* pool_in<2>() { return g_h2; }
template <> __device__ __forceinline__ float* pool_in<3>() { return g_h3; }
template <int L> __device__ __forceinline__ float* pool_out();
template <> __device__ __forceinline__ float* pool_out<1>() { return g_p1; }
template <> __device__ __forceinline__ float* pool_out<2>() { return g_p2; }
template <> __device__ __forceinline__ float* pool_out<3>() { return g_p3; }

// ---------------- helpers ----------------
__device__ __forceinline__ void atomicMaxF(float* addr, float v) {
    if (__float_as_int(v) >= 0) atomicMax((int*)addr, __float_as_int(v));
    else                        atomicMin((unsigned int*)addr, __float_as_uint(v));
}
__device__ __forceinline__ float finz(float v) { return isfinite(v) ? v : 0.0f; }

__device__ __forceinline__ void ffma2(unsigned long long& acc, unsigned long long a,
                                      unsigned long long b) {
    asm("fma.rn.f32x2 %0, %1, %2, %3;" : "=l"(acc) : "l"(a), "l"(b), "l"(acc));
}
__device__ __forceinline__ float unpack_sum(unsigned long long v) {
    float lo, hi;
    asm("mov.b64 {%0, %1}, %2;" : "=f"(lo), "=f"(hi) : "l"(v));
    return lo + hi;
}

__device__ __forceinline__ void basis8(float px, float py, float pz, float* wc, int* flat) {
    float v0 = px * 4.0f, v1 = py * 4.0f, v2 = pz * 4.0f;
    float k0 = fminf(fmaxf(floorf(v0), 0.0f), 3.0f);
    float k1 = fminf(fmaxf(floorf(v1), 0.0f), 3.0f);
    float k2 = fminf(fmaxf(floorf(v2), 0.0f), 3.0f);
    float f0 = v0 - k0, f1 = v1 - k1, f2 = v2 - k2;
    int i0 = (int)k0, i1 = (int)k1, i2 = (int)k2;
#pragma unroll
    for (int c = 0; c < 8; c++) {
        int o0 = c & 1, o1 = (c >> 1) & 1, o2 = (c >> 2) & 1;
        wc[c] = (o0 ? f0 : 1.0f - f0) * (o1 ? f1 : 1.0f - f1) * (o2 ? f2 : 1.0f - f2);
        flat[c] = ((i0 + o0) * 5 + (i1 + o1)) * 5 + (i2 + o2);
    }
}

// ---------------- init ----------------
__global__ void k_init_all() {
    int i = blockIdx.x * blockDim.x + threadIdx.x;
    int stride = gridDim.x * blockDim.x;
    const float NEGINF = -INFINITY;
    for (int j = i; j < N1; j += stride)      { g_p0[j] = NEGINF; g_cnt1[j] = 0; }
    for (int j = i; j < N2 * 32; j += stride) g_p1[j] = NEGINF;
    for (int j = i; j < N2; j += stride)      g_cnt2[j] = 0;
    for (int j = i; j < N3 * 32; j += stride) g_p2[j] = NEGINF;
    for (int j = i; j < N3; j += stride)      g_cnt3[j] = 0;
    for (int j = i; j < B8 * 32; j += stride) g_p3[j] = NEGINF;
}

// ---------------- CSR build (merged over layers) ----------------
__global__ void k_hist_all(const int* __restrict__ ei1, const int* __restrict__ ei2,
                           const int* __restrict__ ei3) {
    int i = blockIdx.x * blockDim.x + threadIdx.x;
    if (i < E1) atomicAdd(&g_cnt1[__ldg(&ei1[E1 + i])], 1);
    if (i < E2) atomicAdd(&g_cnt2[__ldg(&ei2[E2 + i])], 1);
    if (i < E3) atomicAdd(&g_cnt3[__ldg(&ei3[E3 + i])], 1);
}

template <int L>
__device__ __forceinline__ void scan_impl() {
    const int N = BT<L>::N;
    const int CH = N / 1024;
    __shared__ int sums[1024];
    int t = threadIdx.x;
    int base = t * CH;
    int s = 0;
    for (int j = 0; j < CH; j++) s += BT<L>::cnt()[base + j];
    sums[t] = s;
    __syncthreads();
    for (int d = 1; d < 1024; d <<= 1) {
        int v = (t >= d) ? sums[t - d] : 0;
        __syncthreads();
        sums[t] += v;
        __syncthreads();
    }
    int run = sums[t] - s;
    for (int j = 0; j < CH; j++) {
        BT<L>::off()[base + j] = run;
        BT<L>::cur()[base + j] = run;
        run += BT<L>::cnt()[base + j];
    }
    if (t == 1023) BT<L>::off()[N] = run;
}

__global__ void k_scan_all() {
    if (blockIdx.x == 0) scan_impl<1>();
    else if (blockIdx.x == 1) scan_impl<2>();
    else scan_impl<3>();
}

template <int L>
__device__ __forceinline__ void permscat_impl(const int* __restrict__ ei,
                                              const float* __restrict__ pseudo, int i) {
    const int E = BT<L>::E;
    if (i >= E) return;
    int dst = __ldg(&ei[E + i]);
    int pos = atomicAdd(&BT<L>::cur()[dst], 1);
    BT<L>::srcS()[pos] = __ldg(&ei[i]);
    BT<L>::psS()[pos] = make_float4(__ldg(&pseudo[3 * i]), __ldg(&pseudo[3 * i + 1]),
                                    __ldg(&pseudo[3 * i + 2]), 0.0f);
}

__global__ void k_permscat_all(const int* __restrict__ ei1, const float* __restrict__ ps1,
                               const int* __restrict__ ei2, const float* __restrict__ ps2,
                               const int* __restrict__ ei3, const float* __restrict__ ps3) {
    int i = blockIdx.x * blockDim.x + threadIdx.x;
    permscat_impl<1>(ei1, ps1, i);
    permscat_impl<2>(ei2, ps2, i);
    permscat_impl<3>(ei3, ps3, i);
}

// ---------------- pools ----------------
__global__ void k_pool0(const float* __restrict__ x, const int* __restrict__ cluster) {
    int i = blockIdx.x * blockDim.x + threadIdx.x;
    if (i >= N0) return;
    atomicMaxF(&g_p0[__ldg(&cluster[i])], __ldg(&x[i]));
}
template <int L>
__global__ void k_pool32(const int* __restrict__ cluster, int n_in) {
    int i = blockIdx.x * blockDim.x + threadIdx.x;
    if (i >= n_in * 32) return;
    int node = i >> 5, ch = i & 31;
    atomicMaxF(&pool_out<L>()[(size_t)__ldg(&cluster[node]) * 32 + ch], pool_in<L>()[i]);
}

// ---------------- W repack: [k][i][o] -> [k][i/2][o] float2 pairs ----------------
__global__ void k_repackW(const float* __restrict__ W2, const float* __restrict__ W3) {
    int idx = blockIdx.x * blockDim.x + threadIdx.x;
    if (idx >= KBINS * 512) return;
    int k = idx >> 9, r = idx & 511;
    int i2 = r >> 5, o = r & 31;
    g_Wp2[idx] = make_float2(__ldg(&W2[k * 1024 + (2 * i2) * 32 + o]),
                             __ldg(&W2[k * 1024 + (2 * i2 + 1) * 32 + o]));
    g_Wp3[idx] = make_float2(__ldg(&W3[k * 1024 + (2 * i2) * 32 + o]),
                             __ldg(&W3[k * 1024 + (2 * i2 + 1) * 32 + o]));
}

// ---------------- conv1 direct (cin=1): warp per node, W1 in smem ----------------
__global__ void k_conv1(const float* __restrict__ W1, const float* __restrict__ root1,
                        const float* __restrict__ b1) {
    __shared__ float W1s[KBINS * 32];
    int tid = threadIdx.x;
    for (int idx = tid; idx < KBINS * 32; idx += 256) W1s[idx] = __ldg(&W1[idx]);
    __syncthreads();
    int w = tid >> 5, lane = tid & 31;
    int node = blockIdx.x * 8 + w;
    int beg = g_off1[node], end = g_off1[node + 1];
    float acc = 0.0f;
    if (beg < end) {
        float4 ps = g_ps1[beg];
        float xj = finz(g_p0[g_src1[beg]]);
        for (int e = beg; e < end; e++) {
            float4 ps_n = ps; float xj_n = 0.0f;
            if (e + 1 < end) {
                ps_n = g_ps1[e + 1];
                xj_n = finz(g_p0[g_src1[e + 1]]);
            }
            float wc[8]; int flat[8];
            basis8(ps.x, ps.y, ps.z, wc, flat);
            float t = 0.0f;
#pragma unroll
            for (int c = 0; c < 8; c++) t += wc[c] * W1s[flat[c] * 32 + lane];
            acc += xj * t;
            ps = ps_n; xj = xj_n;
        }
    }
    int deg = end - beg;
    float d = (float)(deg > 0 ? deg : 1);
    float v = acc / d + finz(g_p0[node]) * __ldg(&root1[lane]) + __ldg(&b1[lane]);
    g_h1[(size_t)node * 32 + lane] = v > 0.0f ? v : expm1f(v);
}

// ---------------- conv2/3 scatter: warp per node, smem H row ----------------
template <int L>
__global__ void k_scatter32() {
    __shared__ float Hs[2][HROW];
    int w = threadIdx.x >> 5, lane = threadIdx.x & 31;
    int node = blockIdx.x * 2 + w;
    float* hrow = Hs[w];
#pragma unroll 4
    for (int j = lane; j < HROW; j += 32) hrow[j] = 0.0f;
    __syncwarp();
    const float* hin = BT<L>::hin();
    const int* srcS = BT<L>::srcS();
    const float4* psS = BT<L>::psS();
    int beg = BT<L>::off()[node], end = BT<L>::off()[node + 1];
    if (beg < end) {
        float4 ps = psS[beg];
        float xv = finz(hin[(size_t)srcS[beg] * 32 + lane]);
        for (int e = beg; e < end; e++) {
            float4 ps_n = ps; float xv_n = 0.0f;
            if (e + 1 < end) {
                ps_n = psS[e + 1];
                xv_n = finz(hin[(size_t)srcS[e + 1] * 32 + lane]);
            }
            float wc[8]; int flat[8];
            basis8(ps.x, ps.y, ps.z, wc, flat);
#pragma unroll
            for (int c = 0; c < 8; c++) hrow[flat[c] * 32 + lane] += wc[c] * xv;
            ps = ps_n; xv = xv_n;
        }
    }
    __syncwarp();
    float* Hg = BT<L>::H() + (size_t)node * HROW;
#pragma unroll 4
    for (int j = lane; j < HROW; j += 32) Hg[j] = hrow[j];
}

// ---------------- conv2/3 contraction: 64 nodes/block, packed f32x2 FMA ----------------
template <int L>
__global__ void k_gemm32(const float* __restrict__ root, const float* __restrict__ bias) {
    __shared__ float2 Wp[512];      // W[k] as [i/2][o] pairs
    __shared__ float Hs[64 * 32];   // 64 node-rows of 32
    int tid = threadIdx.x;          // 256
    int w = tid >> 5, lane = tid & 31;
    size_t nodeBase = (size_t)blockIdx.x * 64;
    unsigned long long acc2[8];
#pragma unroll
    for (int n = 0; n < 8; n++) acc2[n] = 0ull;

    const float* H = BT<L>::H();
    const float2* Wpg = BT<L>::Wp();
    for (int k = 0; k < KBINS; k++) {
        ((float4*)Wp)[tid] = __ldg(&((const float4*)(Wpg + (size_t)k * 512))[tid]);
#pragma unroll
        for (int r = 0; r < 2; r++) {
            int idx = tid + r * 256;
            int nd = idx >> 3, q = idx & 7;
            ((float4*)Hs)[idx] =
                *(const float4*)&H[((nodeBase + nd) * KBINS + k) * 32 + q * 4];
        }
        __syncthreads();
#pragma unroll
        for (int i4 = 0; i4 < 8; i4++) {
            // pair weights for (i=4*i4..4*i4+3) -> two f32x2 at [2*i4], [2*i4+1]
            unsigned long long wA = ((const unsigned long long*)Wp)[(2 * i4) * 32 + lane];
            unsigned long long wB = ((const unsigned long long*)Wp)[(2 * i4 + 1) * 32 + lane];
#pragma unroll
            for (int n = 0; n < 8; n++) {
                ulonglong2 hv = ((const ulonglong2*)Hs)[(w * 8 + n) * 8 + i4];  // broadcast
                ffma2(acc2[n], hv.x, wA);
                ffma2(acc2[n], hv.y, wB);
            }
        }
        __syncthreads();
    }
    // unpack + degree normalize
    float acc[8];
#pragma unroll
    for (int n = 0; n < 8; n++) {
        int node = (int)nodeBase + w * 8 + n;
        int deg = BT<L>::off()[node + 1] - BT<L>::off()[node];
        acc[n] = unpack_sum(acc2[n]) / (float)(deg > 0 ? deg : 1);
    }
    // root term (scalar, once)
    __shared__ float Rs[1024];
    ((float4*)Rs)[tid] = __ldg(&((const float4*)root)[tid]);
    const float* hin = BT<L>::hin();
#pragma unroll
    for (int r = 0; r < 2; r++) {
        int idx = tid + r * 256;
        int nd = idx >> 3, q = idx & 7;
        float4 hv = *(const float4*)&hin[(nodeBase + nd) * 32 + q * 4];
        hv.x = finz(hv.x); hv.y = finz(hv.y); hv.z = finz(hv.z); hv.w = finz(hv.w);
        ((float4*)Hs)[idx] = hv;
    }
    __syncthreads();
#pragma unroll
    for (int i4 = 0; i4 < 8; i4++) {
        float w0 = Rs[(i4 * 4 + 0) * 32 + lane];
        float w1 = Rs[(i4 * 4 + 1) * 32 + lane];
        float w2 = Rs[(i4 * 4 + 2) * 32 + lane];
        float w3 = Rs[(i4 * 4 + 3) * 32 + lane];
#pragma unroll
        for (int n = 0; n < 8; n++) {
            float4 hv = ((float4*)Hs)[(w * 8 + n) * 8 + i4];
            acc[n] += hv.x * w0 + hv.y * w1 + hv.z * w2 + hv.w * w3;
        }
    }
    float bv = __ldg(&bias[lane]);
    float* hout = BT<L>::hout();
#pragma unroll
    for (int n = 0; n < 8; n++) {
        float v = acc[n] + bv;
        hout[(nodeBase + w * 8 + n) * 32 + lane] = v > 0.0f ? v : expm1f(v);
    }
}

// ---------------- FC head + log_softmax ----------------
__global__ void k_fc_head(const float* __restrict__ fcw, const float* __restrict__ fcb,
                          float* __restrict__ out) {
    __shared__ float hs[256];
    __shared__ float lg[10];
    __shared__ float lse;
    int b = blockIdx.x;
    int t = threadIdx.x;
    hs[t] = finz(g_p3[(size_t)b * 256 + t]);
    __syncthreads();
    if (t < 10) {
        float s = __ldg(&fcb[t]);
#pragma unroll 8
        for (int i = 0; i < 256; i++) s += hs[i] * __ldg(&fcw[i * 10 + t]);
        lg[t] = s;
    }
    __syncthreads();
    if (t == 0) {
        float m = lg[0];
        for (int j = 1; j < 10; j++) m = fmaxf(m, lg[j]);
        float se = 0.0f;
        for (int j = 0; j < 10; j++) se += expf(lg[j] - m);
        lse = m + logf(se);
    }
    __syncthreads();
    if (t < 10) out[b * 10 + t] = lg[t] - lse;
}

// ---------------- launcher ----------------
static inline int cdiv(long long a, int b) { return (int)((a + b - 1) / b); }

extern "C" void kernel_launch(void* const* d_in, const int* in_sizes, int n_in,
                              void* d_out, int out_size) {
    const float* x        = (const float*)d_in[0];
    const int*   cluster0 = (const int*)d_in[1];
    const int*   ei1      = (const int*)d_in[2];
    const float* pseudo1  = (const float*)d_in[3];
    const int*   cluster1 = (const int*)d_in[4];
    const int*   ei2      = (const int*)d_in[5];
    const float* pseudo2  = (const float*)d_in[6];
    const int*   cluster2 = (const int*)d_in[7];
    const int*   ei3      = (const int*)d_in[8];
    const float* pseudo3  = (const float*)d_in[9];
    const int*   cluster3 = (const int*)d_in[10];
    const float* W1       = (const float*)d_in[11];
    const float* root1    = (const float*)d_in[12];
    const float* b1       = (const float*)d_in[13];
    const float* W2       = (const float*)d_in[14];
    const float* root2    = (const float*)d_in[15];
    const float* b2       = (const float*)d_in[16];
    const float* W3       = (const float*)d_in[17];
    const float* root3    = (const float*)d_in[18];
    const float* b3       = (const float*)d_in[19];
    const float* fcw      = (const float*)d_in[20];
    const float* fcb      = (const float*)d_in[21];
    float* out = (float*)d_out;

    const int TB = 256;

    k_init_all<<<512, TB>>>();                                   // 0
    k_hist_all<<<cdiv(E1, TB), TB>>>(ei1, ei2, ei3);             // 1
    k_scan_all<<<3, 1024>>>();                                   // 2
    k_pool0<<<cdiv(N0, TB), TB>>>(x, cluster0);                  // 3
    k_permscat_all<<<cdiv(E1, TB), TB>>>(ei1, pseudo1, ei2, pseudo2, ei3, pseudo3);  // 4
    k_conv1<<<N1 / 8, 256>>>(W1, root1, b1);                     // 5
    k_repackW<<<cdiv(KBINS * 512, TB), TB>>>(W2, W3);            // 6

    k_pool32<1><<<cdiv(N1 * 32, TB), TB>>>(cluster1, N1);        // 7
    k_scatter32<2><<<N2 / 2, 64>>>();                            // 8
    k_gemm32<2><<<N2 / 64, 256>>>(root2, b2);                    // 9

    k_pool32<2><<<cdiv(N2 * 32, TB), TB>>>(cluster2, N2);        // 10
    k_scatter32<3><<<N3 / 2, 64>>>();                            // 11
    k_gemm32<3><<<N3 / 64, 256>>>(root3, b3);                    // 12

    k_pool32<3><<<cdiv(N3 * 32, TB), TB>>>(cluster3, N3);        // 13
    k_fc_head<<<NBATCH, 256>>>(fcw, fcb, out);                   // 14
}